// round 4
// baseline (speedup 1.0000x reference)
#include <cuda_runtime.h>
#include <math.h>

#define TLEN    6000
#define NP      199
#define PLEN    60
#define PSTRIDE 30
#define NSP     30
#define NFREQ   16
#define NM      13
#define NS      9
#define NFEAT   22
#define TM      128
#define MAXROWS (1024*NP)

// 22-dim normalized feature rows (203776 x 22)
__device__ float g_F[(size_t)MAXROWS * NFEAT];

__device__ __forceinline__ float geluf(float v){
    return 0.5f * v * (1.0f + erff(v * 0.7071067811865476f));
}

// ---- packed f32x2 helpers ----
__device__ __forceinline__ unsigned long long pk2(float a, float b){
    unsigned long long r;
    asm("mov.b64 %0, {%1, %2};" : "=l"(r)
        : "r"(__float_as_uint(a)), "r"(__float_as_uint(b)));
    return r;
}
__device__ __forceinline__ unsigned long long ffma2(unsigned long long a,
                                                    unsigned long long b,
                                                    unsigned long long c){
    unsigned long long d;
    asm("fma.rn.f32x2 %0, %1, %2, %3;" : "=l"(d) : "l"(a), "l"(b), "l"(c));
    return d;
}
__device__ __forceinline__ float lo2(unsigned long long a){
    return __uint_as_float((unsigned)(a & 0xffffffffull));
}
__device__ __forceinline__ float hi2(unsigned long long a){
    return __uint_as_float((unsigned)(a >> 32));
}

__device__ __forceinline__ float freqf(int k){
    return (float)(((double)k * 200.0) / 30.0);
}

// ============================================================
// Kernel A: per-patch features + group layernorms -> g_F
//   symmetric real DFT, fully unrolled -> all arrays in regs
// ============================================================
__global__ __launch_bounds__(256) void feat_kernel(
    const float* __restrict__ x,
    const float* __restrict__ gm, const float* __restrict__ bm,
    const float* __restrict__ gs, const float* __restrict__ bs)
{
    __shared__ float sx[TLEN];
    __shared__ float cosT[NFREQ * 16];
    __shared__ float sinT[NFREQ * 16];
    __shared__ float hannS[NSP];

    const int tid = threadIdx.x;
    {
        const float4* xg = (const float4*)(x + (size_t)blockIdx.x * TLEN);
        float4* s4 = (float4*)sx;
        for (int i = tid; i < TLEN/4; i += 256) s4[i] = xg[i];
    }
    for (int i = tid; i < NFREQ*16; i += 256) {
        int k = i >> 4, t = i & 15;
        double sv, cv;
        sincospi(2.0 * (double)(k * t) / 30.0, &sv, &cv);
        cosT[i] = (float)cv;
        sinT[i] = (float)sv;
    }
    if (tid < NSP)
        hannS[tid] = (float)(0.5 * (1.0 - cospi(2.0 * (double)tid / 30.0)));
    __syncthreads();
    if (tid >= NP) return;

    const int off = tid * PSTRIDE;
    float* frow = &g_F[((size_t)blockIdx.x * NP + tid) * NFEAT];

    // ---- morph pass 1 (streaming) ----
    float v0 = sx[off];
    float mx = v0, mn = v0, sum = v0;
    float sumsq = v0 * v0;
    float amax = fabsf(v0); int aidx = 0;
    float prev = v0;
    float tsg = v0 + 1e-10f;
    int   sprev = (tsg > 0.0f) - (tsg < 0.0f);
    float dmax = -INFINITY, dmin = INFINITY, dabs = 0.0f;
    int zc = 0;
    #pragma unroll
    for (int t = 1; t < PLEN; t++) {
        float v = sx[off + t];
        mx = fmaxf(mx, v); mn = fminf(mn, v);
        sum += v; sumsq = fmaf(v, v, sumsq);
        float a = fabsf(v);
        if (a > amax) { amax = a; aidx = t; }
        float d = v - prev;
        dmax = fmaxf(dmax, d); dmin = fminf(dmin, d); dabs += fabsf(d);
        float tg = v + 1e-10f;
        int sg = (tg > 0.0f) - (tg < 0.0f);
        zc += (sg != sprev);
        sprev = sg; prev = v;
    }
    float mean = sum * (1.0f/60.0f);

    // ---- morph pass 2: central moments ----
    float m2 = 0.f, m3 = 0.f, m4 = 0.f;
    #pragma unroll
    for (int t = 0; t < PLEN; t++) {
        float c = sx[off + t] - mean;
        float c2 = c * c;
        m2 += c2; m3 = fmaf(c2, c, m3); m4 = fmaf(c2, c2, m4);
    }
    m2 *= (1.0f/60.0f); m3 *= (1.0f/60.0f); m4 *= (1.0f/60.0f);
    float stdv = sqrtf(m2);

    {
        float morph[NM];
        morph[0] = mx; morph[1] = mn; morph[2] = mx - mn; morph[3] = mean;
        morph[4] = stdv;
        morph[5] = (float)aidx * (1.0f/60.0f);
        morph[6] = dmax; morph[7] = dmin;
        morph[8] = dabs * (1.0f/59.0f);
        morph[9] = (float)zc * (1.0f/60.0f);
        morph[10] = sumsq;
        morph[11] = m4 / (m2 * m2) - 3.0f;
        morph[12] = m3 / (m2 * stdv);
        #pragma unroll
        for (int i = 0; i < NM; i++) if (!isfinite(morph[i])) morph[i] = 0.0f;

        float mu = 0.f;
        #pragma unroll
        for (int i = 0; i < NM; i++) mu += morph[i];
        mu *= (1.0f/13.0f);
        float var = 0.f;
        #pragma unroll
        for (int i = 0; i < NM; i++) { float d = morph[i]-mu; var = fmaf(d,d,var); }
        var *= (1.0f/13.0f);
        float scl = rsqrtf(var + 1e-5f);
        #pragma unroll
        for (int i = 0; i < NM; i++)
            frow[i] = fmaf((morph[i]-mu)*scl, gm[i], bm[i]);
    }

    // ---- Welch PSD: sequential segments, symmetric DFT (fully unrolled) ----
    float psd[NFREQ];
    #pragma unroll
    for (int k = 0; k < NFREQ; k++) psd[k] = 0.0f;

    #pragma unroll
    for (int seg = 0; seg < 3; seg++) {
        const int sb = off + seg * 15;
        float y[NSP];
        float sm = 0.f;
        #pragma unroll
        for (int t = 0; t < NSP; t++) { y[t] = sx[sb + t]; sm += y[t]; }
        sm *= (1.0f/30.0f);
        #pragma unroll
        for (int t = 0; t < NSP; t++) y[t] = (y[t] - sm) * hannS[t];

        float ye[16], yo[16];
        ye[0] = y[0]; ye[15] = y[15];
        yo[0] = 0.f;  yo[15] = 0.f;
        #pragma unroll
        for (int t = 1; t < 15; t++) {
            ye[t] = y[t] + y[30 - t];
            yo[t] = y[t] - y[30 - t];
        }
        #pragma unroll
        for (int k = 0; k < NFREQ; k++) {
            const float* ck = &cosT[k * 16];
            const float* sk = &sinT[k * 16];
            float re = ye[0] * ck[0];
            float im = 0.f;
            #pragma unroll
            for (int t = 1; t < 15; t++) {
                re = fmaf(ye[t], ck[t], re);
                im = fmaf(yo[t], sk[t], im);
            }
            re = fmaf(ye[15], ck[15], re);
            psd[k] = fmaf(re, re, fmaf(im, im, psd[k]));
        }
    }
    #pragma unroll
    for (int k = 0; k < NFREQ; k++) {
        float sc = (k == 0 || k == NFREQ-1) ? (1.0f/6750.0f) : (2.0f/6750.0f);
        psd[k] *= sc;
    }

    // ---- spectral features ----
    float total = 0.f;
    #pragma unroll
    for (int k = 0; k < NFREQ; k++) total += psd[k];
    total += 1e-12f;
    float inv = 1.0f / total;

    float b1v = psd[1];
    float b3v = psd[2] + psd[3] + psd[4];
    float b4v = 0.f;
    #pragma unroll
    for (int k = 5; k <= 14; k++) b4v += psd[k];

    float pmax = psd[0]; int pkk = 0;
    #pragma unroll
    for (int k = 1; k < NFREQ; k++)
        if (psd[k] > pmax) { pmax = psd[k]; pkk = k; }

    float thr = 0.95f * total;
    float csum = 0.f; int ek = 0; bool fnd = false;
    #pragma unroll
    for (int k = 0; k < NFREQ; k++) {
        csum += psd[k];
        if (!fnd && csum >= thr) { ek = k; fnd = true; }
    }
    float ent = 0.f;
    #pragma unroll
    for (int k = 0; k < NFREQ; k++) {
        float pn = psd[k] * inv;
        ent -= pn * log2f(pn + 1e-12f);
    }

    float spec[NS];
    spec[0] = 0.0f;            // (1,4): no bins
    spec[1] = b1v * inv;       // (4,8): bin 1
    spec[2] = 0.0f;            // (8,13): no bins
    spec[3] = b3v * inv;       // (13,30): bins 2..4
    spec[4] = b4v * inv;       // (30,99): bins 5..14
    spec[5] = freqf(pkk);
    spec[6] = freqf(ek);
    spec[7] = ent;
    spec[8] = total;
    #pragma unroll
    for (int i = 0; i < NS; i++) if (!isfinite(spec[i])) spec[i] = 0.0f;

    {
        float mu = 0.f;
        #pragma unroll
        for (int i = 0; i < NS; i++) mu += spec[i];
        mu *= (1.0f/9.0f);
        float var = 0.f;
        #pragma unroll
        for (int i = 0; i < NS; i++) { float d = spec[i]-mu; var = fmaf(d,d,var); }
        var *= (1.0f/9.0f);
        float scl = rsqrtf(var + 1e-5f);
        #pragma unroll
        for (int i = 0; i < NS; i++)
            frow[NM + i] = fmaf((spec[i]-mu)*scl, gs[i], bs[i]);
    }
}

// ============================================================
// Kernel B: persistent MLP  (22 -> 128 GELU -> 256 -> LN)
// Warp-autonomous: no __syncthreads inside the tile loop.
// ============================================================
// smem floats: W2 32768 | hs2 16384 | Fs 2816 | W1 2816 | b1 128 | b2/go/bo 768
#define SMEM_FLOATS (32768 + 16384 + 2816 + 2816 + 128 + 256 + 256 + 256)

__global__ __launch_bounds__(512, 1) void mlp_kernel(
    const float* __restrict__ W1, const float* __restrict__ b1,
    const float* __restrict__ W2, const float* __restrict__ b2,
    const float* __restrict__ go, const float* __restrict__ bo,
    float* __restrict__ out, int nRows)
{
    extern __shared__ float sm[];
    float* W2s = sm;                   // [k][256]
    float* hs2 = W2s + 32768;          // per-warp: 4 pairs x 128 k, float2
    float* Fs  = hs2 + 16384;          // per-warp: 8 rows x 22
    float* W1s = Fs + 2816;            // [k][128]
    float* b1s = W1s + 2816;
    float* b2s = b1s + 128;
    float* gos = b2s + 256;
    float* bos = gos + 256;

    const int tid = threadIdx.x;
    for (int i = tid; i < 8192; i += 512) ((float4*)W2s)[i] = ((const float4*)W2)[i];
    for (int i = tid; i < 2816; i += 512) W1s[i] = W1[i];
    if (tid < 128) b1s[tid] = b1[tid];
    for (int i = tid; i < 256; i += 512) { b2s[i]=b2[i]; gos[i]=go[i]; bos[i]=bo[i]; }
    __syncthreads();

    const int wid  = tid >> 5;          // 0..15
    const int lane = tid & 31;
    const int r0   = wid * 8;           // warp's rows within tile
    const int c1   = lane * 4;          // GEMM1 cols
    const int c2   = lane * 8;          // GEMM2 cols
    float* Fw = Fs + wid * (8 * NFEAT);                       // 176 floats
    const unsigned long long* Hw64;
    float2* Hw = (float2*)(hs2 + wid * 1024);                 // [pair*128 + k]
    Hw64 = (const unsigned long long*)Hw;

    const int nTiles = (nRows + TM - 1) / TM;

    for (int tile = blockIdx.x; tile < nTiles; tile += gridDim.x) {
        const int rowBase = tile * TM;
        const int wRow = rowBase + r0;

        // per-warp F staging (8 rows x 22, contiguous 176 floats)
        {
            const float* src = &g_F[(size_t)wRow * NFEAT];
            #pragma unroll
            for (int i = lane; i < 8 * NFEAT; i += 32)
                Fw[i] = (wRow + i / NFEAT < nRows) ? src[i] : 0.0f;
        }
        __syncwarp();

        // GEMM1 + bias + GELU -> Hw as row-pair float2 [pair][k]
        {
            float acc[8][4];
            #pragma unroll
            for (int i = 0; i < 8; i++)
                #pragma unroll
                for (int j = 0; j < 4; j++) acc[i][j] = 0.0f;
            #pragma unroll
            for (int k = 0; k < NFEAT; k++) {
                float4 w = *(const float4*)&W1s[k*128 + c1];
                #pragma unroll
                for (int i = 0; i < 8; i++) {
                    float a = Fw[i*NFEAT + k];
                    acc[i][0] = fmaf(a, w.x, acc[i][0]);
                    acc[i][1] = fmaf(a, w.y, acc[i][1]);
                    acc[i][2] = fmaf(a, w.z, acc[i][2]);
                    acc[i][3] = fmaf(a, w.w, acc[i][3]);
                }
            }
            float bv[4] = { b1s[c1], b1s[c1+1], b1s[c1+2], b1s[c1+3] };
            #pragma unroll
            for (int p = 0; p < 4; p++) {
                #pragma unroll
                for (int j = 0; j < 4; j++) {
                    float h0 = geluf(acc[2*p  ][j] + bv[j]);
                    float h1 = geluf(acc[2*p+1][j] + bv[j]);
                    Hw[p*128 + c1 + j] = make_float2(h0, h1);
                }
            }
        }
        __syncwarp();

        // GEMM2: 4 row-pairs x 8 cols; a-operand is a direct 64-bit LDS
        unsigned long long acc2[4][8];
        #pragma unroll
        for (int p = 0; p < 4; p++)
            #pragma unroll
            for (int j = 0; j < 8; j++) acc2[p][j] = 0ull;

        #pragma unroll 4
        for (int k = 0; k < 128; k++) {
            float4 wA = *(const float4*)&W2s[k*256 + c2];
            float4 wB = *(const float4*)&W2s[k*256 + c2 + 4];
            unsigned long long bw[8];
            bw[0] = pk2(wA.x, wA.x); bw[1] = pk2(wA.y, wA.y);
            bw[2] = pk2(wA.z, wA.z); bw[3] = pk2(wA.w, wA.w);
            bw[4] = pk2(wB.x, wB.x); bw[5] = pk2(wB.y, wB.y);
            bw[6] = pk2(wB.z, wB.z); bw[7] = pk2(wB.w, wB.w);
            #pragma unroll
            for (int p = 0; p < 4; p++) {
                unsigned long long a2 = Hw64[p*128 + k];
                #pragma unroll
                for (int j = 0; j < 8; j++)
                    acc2[p][j] = ffma2(a2, bw[j], acc2[p][j]);
            }
        }

        // epilogue: +b2, per-row LayerNorm over 256 (warp = one row group)
        float bb[8], gg[8], oo[8];
        #pragma unroll
        for (int j = 0; j < 8; j++) {
            bb[j] = b2s[c2+j]; gg[j] = gos[c2+j]; oo[j] = bos[c2+j];
        }
        #pragma unroll
        for (int p = 0; p < 4; p++) {
            float vl[8], vh[8];
            #pragma unroll
            for (int j = 0; j < 8; j++) {
                vl[j] = lo2(acc2[p][j]) + bb[j];
                vh[j] = hi2(acc2[p][j]) + bb[j];
            }
            float sl = 0.f, sh = 0.f;
            #pragma unroll
            for (int j = 0; j < 8; j++) { sl += vl[j]; sh += vh[j]; }
            #pragma unroll
            for (int off = 16; off >= 1; off >>= 1) {
                sl += __shfl_xor_sync(0xffffffffu, sl, off);
                sh += __shfl_xor_sync(0xffffffffu, sh, off);
            }
            float mul = sl * (1.0f/256.0f);
            float muh = sh * (1.0f/256.0f);
            float ql = 0.f, qh = 0.f;
            #pragma unroll
            for (int j = 0; j < 8; j++) {
                float dl = vl[j]-mul; ql = fmaf(dl,dl,ql);
                float dh = vh[j]-muh; qh = fmaf(dh,dh,qh);
            }
            #pragma unroll
            for (int off = 16; off >= 1; off >>= 1) {
                ql += __shfl_xor_sync(0xffffffffu, ql, off);
                qh += __shfl_xor_sync(0xffffffffu, qh, off);
            }
            float rsl = rsqrtf(ql * (1.0f/256.0f) + 1e-5f);
            float rsh = rsqrtf(qh * (1.0f/256.0f) + 1e-5f);

            int rowL = wRow + 2*p;
            if (rowL < nRows) {
                float4 o1, o2;
                o1.x = fmaf((vl[0]-mul)*rsl, gg[0], oo[0]);
                o1.y = fmaf((vl[1]-mul)*rsl, gg[1], oo[1]);
                o1.z = fmaf((vl[2]-mul)*rsl, gg[2], oo[2]);
                o1.w = fmaf((vl[3]-mul)*rsl, gg[3], oo[3]);
                o2.x = fmaf((vl[4]-mul)*rsl, gg[4], oo[4]);
                o2.y = fmaf((vl[5]-mul)*rsl, gg[5], oo[5]);
                o2.z = fmaf((vl[6]-mul)*rsl, gg[6], oo[6]);
                o2.w = fmaf((vl[7]-mul)*rsl, gg[7], oo[7]);
                float* op = &out[(size_t)rowL*256 + c2];
                *(float4*)op = o1; *(float4*)(op+4) = o2;
            }
            if (rowL + 1 < nRows) {
                float4 o1, o2;
                o1.x = fmaf((vh[0]-muh)*rsh, gg[0], oo[0]);
                o1.y = fmaf((vh[1]-muh)*rsh, gg[1], oo[1]);
                o1.z = fmaf((vh[2]-muh)*rsh, gg[2], oo[2]);
                o1.w = fmaf((vh[3]-muh)*rsh, gg[3], oo[3]);
                o2.x = fmaf((vh[4]-muh)*rsh, gg[4], oo[4]);
                o2.y = fmaf((vh[5]-muh)*rsh, gg[5], oo[5]);
                o2.z = fmaf((vh[6]-muh)*rsh, gg[6], oo[6]);
                o2.w = fmaf((vh[7]-muh)*rsh, gg[7], oo[7]);
                float* op = &out[(size_t)(rowL+1)*256 + c2];
                *(float4*)op = o1; *(float4*)(op+4) = o2;
            }
        }
        __syncwarp();  // hs2/Fs reuse safety within warp
    }
}

extern "C" void kernel_launch(void* const* d_in, const int* in_sizes, int n_in,
                              void* d_out, int out_size) {
    const float* x  = (const float*)d_in[0];
    const float* gm = (const float*)d_in[1];
    const float* bm = (const float*)d_in[2];
    const float* gs = (const float*)d_in[3];
    const float* bs = (const float*)d_in[4];
    const float* W1 = (const float*)d_in[5];
    const float* b1 = (const float*)d_in[6];
    const float* W2 = (const float*)d_in[7];
    const float* b2 = (const float*)d_in[8];
    const float* go = (const float*)d_in[9];
    const float* bo = (const float*)d_in[10];

    int B = in_sizes[0] / TLEN;
    int nRows = B * NP;

    cudaFuncSetAttribute(mlp_kernel, cudaFuncAttributeMaxDynamicSharedMemorySize,
                         SMEM_FLOATS * (int)sizeof(float));

    feat_kernel<<<B, 256>>>(x, gm, bm, gs, bs);
    mlp_kernel<<<148, 512, SMEM_FLOATS * (int)sizeof(float)>>>(
        W1, b1, W2, b2, go, bo, (float*)d_out, nRows);
}

// round 5
// speedup vs baseline: 1.5232x; 1.5232x over previous
#include <cuda_runtime.h>
#include <math.h>

#define TLEN    6000
#define NP      199
#define PLEN    60
#define PSTRIDE 30
#define NSP     30
#define NFREQ   16
#define NM      13
#define NS      9
#define NFEAT   22
#define TM      128
#define MAXROWS (1024*NP)

// 22-dim normalized feature rows (203776 x 22)
__device__ float g_F[(size_t)MAXROWS * NFEAT];

__device__ __forceinline__ float geluf(float v){
    return 0.5f * v * (1.0f + erff(v * 0.7071067811865476f));
}

// ---- packed f32x2 helpers ----
__device__ __forceinline__ unsigned long long pk2(float a, float b){
    unsigned long long r;
    asm("mov.b64 %0, {%1, %2};" : "=l"(r)
        : "r"(__float_as_uint(a)), "r"(__float_as_uint(b)));
    return r;
}
__device__ __forceinline__ unsigned long long ffma2(unsigned long long a,
                                                    unsigned long long b,
                                                    unsigned long long c){
    unsigned long long d;
    asm("fma.rn.f32x2 %0, %1, %2, %3;" : "=l"(d) : "l"(a), "l"(b), "l"(c));
    return d;
}
__device__ __forceinline__ float lo2(unsigned long long a){
    return __uint_as_float((unsigned)(a & 0xffffffffull));
}
__device__ __forceinline__ float hi2(unsigned long long a){
    return __uint_as_float((unsigned)(a >> 32));
}

__device__ __forceinline__ float freqf(int k){
    return (float)(((double)k * 200.0) / 30.0);
}

// ============================================================
// Kernel A: per-patch features + group layernorms -> g_F
//   - 3 Welch segments FUSED per k (single psd write)
//   - hann-symmetry folding (half the DFT FMAs, t=0 term = 0)
//   - rolled k loop (small code), psd via padded smem (no local)
// ============================================================
__global__ __launch_bounds__(256) void feat_kernel(
    const float* __restrict__ x,
    const float* __restrict__ gm, const float* __restrict__ bm,
    const float* __restrict__ gs, const float* __restrict__ bs)
{
    __shared__ float sx[TLEN];
    __shared__ float cosT[NFREQ * 16];
    __shared__ float sinT[NFREQ * 16];
    __shared__ float hannS[NSP];
    __shared__ float psdS[NFREQ * 200];

    const int tid = threadIdx.x;
    {
        const float4* xg = (const float4*)(x + (size_t)blockIdx.x * TLEN);
        float4* s4 = (float4*)sx;
        for (int i = tid; i < TLEN/4; i += 256) s4[i] = xg[i];
    }
    for (int i = tid; i < NFREQ*16; i += 256) {
        int k = i >> 4, t = i & 15;
        double sv, cv;
        sincospi(2.0 * (double)(k * t) / 30.0, &sv, &cv);
        cosT[i] = (float)cv;
        sinT[i] = (float)sv;
    }
    if (tid < NSP)
        hannS[tid] = (float)(0.5 * (1.0 - cospi(2.0 * (double)tid / 30.0)));
    __syncthreads();
    if (tid >= NP) return;

    const int off = tid * PSTRIDE;
    float* frow = &g_F[((size_t)blockIdx.x * NP + tid) * NFEAT];

    // ---- morph pass 1 (streaming) ----
    float v0 = sx[off];
    float mx = v0, mn = v0, sum = v0;
    float sumsq = v0 * v0;
    float amax = fabsf(v0); int aidx = 0;
    float prev = v0;
    float tsg = v0 + 1e-10f;
    int   sprev = (tsg > 0.0f) - (tsg < 0.0f);
    float dmax = -INFINITY, dmin = INFINITY, dabs = 0.0f;
    int zc = 0;
    #pragma unroll
    for (int t = 1; t < PLEN; t++) {
        float v = sx[off + t];
        mx = fmaxf(mx, v); mn = fminf(mn, v);
        sum += v; sumsq = fmaf(v, v, sumsq);
        float a = fabsf(v);
        if (a > amax) { amax = a; aidx = t; }
        float d = v - prev;
        dmax = fmaxf(dmax, d); dmin = fminf(dmin, d); dabs += fabsf(d);
        float tg = v + 1e-10f;
        int sg = (tg > 0.0f) - (tg < 0.0f);
        zc += (sg != sprev);
        sprev = sg; prev = v;
    }
    float mean = sum * (1.0f/60.0f);

    // ---- morph pass 2: central moments ----
    float m2 = 0.f, m3 = 0.f, m4 = 0.f;
    #pragma unroll
    for (int t = 0; t < PLEN; t++) {
        float c = sx[off + t] - mean;
        float c2 = c * c;
        m2 += c2; m3 = fmaf(c2, c, m3); m4 = fmaf(c2, c2, m4);
    }
    m2 *= (1.0f/60.0f); m3 *= (1.0f/60.0f); m4 *= (1.0f/60.0f);
    float stdv = sqrtf(m2);

    {
        float morph[NM];
        morph[0] = mx; morph[1] = mn; morph[2] = mx - mn; morph[3] = mean;
        morph[4] = stdv;
        morph[5] = (float)aidx * (1.0f/60.0f);
        morph[6] = dmax; morph[7] = dmin;
        morph[8] = dabs * (1.0f/59.0f);
        morph[9] = (float)zc * (1.0f/60.0f);
        morph[10] = sumsq;
        morph[11] = m4 / (m2 * m2) - 3.0f;
        morph[12] = m3 / (m2 * stdv);
        #pragma unroll
        for (int i = 0; i < NM; i++) if (!isfinite(morph[i])) morph[i] = 0.0f;

        float mu = 0.f;
        #pragma unroll
        for (int i = 0; i < NM; i++) mu += morph[i];
        mu *= (1.0f/13.0f);
        float var = 0.f;
        #pragma unroll
        for (int i = 0; i < NM; i++) { float d = morph[i]-mu; var = fmaf(d,d,var); }
        var *= (1.0f/13.0f);
        float scl = rsqrtf(var + 1e-5f);
        #pragma unroll
        for (int i = 0; i < NM; i++)
            frow[i] = fmaf((morph[i]-mu)*scl, gm[i], bm[i]);
    }

    // ---- Welch: symmetry-folded even/odd sequences for the 3 segments ----
    // ye[t] = (y[t]+y[30-t]-2*mean)*w[t]  (t=1..14), ye[15]=(y[15]-mean)*w[15]
    // yo[t] = (y[t]-y[30-t])*w[t]         (t=1..14);  t=0 term vanishes (w[0]=0)
    float ye0[16], yo0[15], ye1[16], yo1[15], ye2[16], yo2[15];

    #define FOLD_SEG(YE, YO, SB) { \
        float s = 0.f; \
        _Pragma("unroll") \
        for (int t = 0; t < NSP; t++) s += sx[(SB) + t]; \
        s *= (1.0f/30.0f); \
        float s2 = 2.0f * s; \
        _Pragma("unroll") \
        for (int t = 1; t < 15; t++) { \
            float a = sx[(SB) + t]; \
            float b = sx[(SB) + 30 - t]; \
            float w = hannS[t]; \
            YE[t] = (a + b - s2) * w; \
            YO[t] = (a - b) * w; \
        } \
        YE[15] = sx[(SB) + 15] - s; \
    }

    FOLD_SEG(ye0, yo0, off)
    FOLD_SEG(ye1, yo1, off + 15)
    FOLD_SEG(ye2, yo2, off + 30)
    #undef FOLD_SEG

    for (int k = 0; k < NFREQ; k++) {
        const float* ck = &cosT[k * 16];
        const float* sk = &sinT[k * 16];
        float re0 = 0.f, im0 = 0.f, re1 = 0.f, im1 = 0.f, re2 = 0.f, im2 = 0.f;
        #pragma unroll
        for (int t = 1; t < 15; t++) {
            float c = ck[t], si = sk[t];
            re0 = fmaf(ye0[t], c, re0); im0 = fmaf(yo0[t], si, im0);
            re1 = fmaf(ye1[t], c, re1); im1 = fmaf(yo1[t], si, im1);
            re2 = fmaf(ye2[t], c, re2); im2 = fmaf(yo2[t], si, im2);
        }
        float c15 = ck[15];
        re0 = fmaf(ye0[15], c15, re0);
        re1 = fmaf(ye1[15], c15, re1);
        re2 = fmaf(ye2[15], c15, re2);
        float p = fmaf(re0,re0,im0*im0) + fmaf(re1,re1,im1*im1) + fmaf(re2,re2,im2*im2);
        float sc = (k == 0 || k == NFREQ-1) ? (1.0f/6750.0f) : (2.0f/6750.0f);
        psdS[k*200 + tid] = p * sc;
    }

    // reload psd into registers (unrolled -> no local memory)
    float psd[NFREQ];
    #pragma unroll
    for (int k = 0; k < NFREQ; k++) psd[k] = psdS[k*200 + tid];

    // ---- spectral features (all in registers) ----
    float total = 0.f;
    #pragma unroll
    for (int k = 0; k < NFREQ; k++) total += psd[k];
    total += 1e-12f;
    float inv = 1.0f / total;

    float b1v = psd[1];
    float b3v = psd[2] + psd[3] + psd[4];
    float b4v = 0.f;
    #pragma unroll
    for (int k = 5; k <= 14; k++) b4v += psd[k];

    float pmax = psd[0]; int pkk = 0;
    #pragma unroll
    for (int k = 1; k < NFREQ; k++)
        if (psd[k] > pmax) { pmax = psd[k]; pkk = k; }

    float thr = 0.95f * total;
    float csum = 0.f; int ek = 0; bool fnd = false;
    #pragma unroll
    for (int k = 0; k < NFREQ; k++) {
        csum += psd[k];
        if (!fnd && csum >= thr) { ek = k; fnd = true; }
    }
    float ent = 0.f;
    #pragma unroll
    for (int k = 0; k < NFREQ; k++) {
        float pn = psd[k] * inv;
        ent -= pn * log2f(pn + 1e-12f);
    }

    float spec[NS];
    spec[0] = 0.0f;            // (1,4): no bins
    spec[1] = b1v * inv;       // (4,8): bin 1
    spec[2] = 0.0f;            // (8,13): no bins
    spec[3] = b3v * inv;       // (13,30): bins 2..4
    spec[4] = b4v * inv;       // (30,99): bins 5..14
    spec[5] = freqf(pkk);
    spec[6] = freqf(ek);
    spec[7] = ent;
    spec[8] = total;
    #pragma unroll
    for (int i = 0; i < NS; i++) if (!isfinite(spec[i])) spec[i] = 0.0f;

    {
        float mu = 0.f;
        #pragma unroll
        for (int i = 0; i < NS; i++) mu += spec[i];
        mu *= (1.0f/9.0f);
        float var = 0.f;
        #pragma unroll
        for (int i = 0; i < NS; i++) { float d = spec[i]-mu; var = fmaf(d,d,var); }
        var *= (1.0f/9.0f);
        float scl = rsqrtf(var + 1e-5f);
        #pragma unroll
        for (int i = 0; i < NS; i++)
            frow[NM + i] = fmaf((spec[i]-mu)*scl, gs[i], bs[i]);
    }
}

// ============================================================
// Kernel B: persistent MLP  (22 -> 128 GELU -> 256 -> LN)
// Warp-autonomous: no __syncthreads inside the tile loop.
// ============================================================
// smem floats: W2 32768 | hs2 16384 | Fs 2816 | W1 2816 | b1 128 | b2/go/bo 768
#define SMEM_FLOATS (32768 + 16384 + 2816 + 2816 + 128 + 256 + 256 + 256)

__global__ __launch_bounds__(512, 1) void mlp_kernel(
    const float* __restrict__ W1, const float* __restrict__ b1,
    const float* __restrict__ W2, const float* __restrict__ b2,
    const float* __restrict__ go, const float* __restrict__ bo,
    float* __restrict__ out, int nRows)
{
    extern __shared__ float sm[];
    float* W2s = sm;                   // [k][256]
    float* hs2 = W2s + 32768;          // per-warp: 4 pairs x 128 k, float2
    float* Fs  = hs2 + 16384;          // per-warp: 8 rows x 22
    float* W1s = Fs + 2816;            // [k][128]
    float* b1s = W1s + 2816;
    float* b2s = b1s + 128;
    float* gos = b2s + 256;
    float* bos = gos + 256;

    const int tid = threadIdx.x;
    for (int i = tid; i < 8192; i += 512) ((float4*)W2s)[i] = ((const float4*)W2)[i];
    for (int i = tid; i < 2816; i += 512) W1s[i] = W1[i];
    if (tid < 128) b1s[tid] = b1[tid];
    for (int i = tid; i < 256; i += 512) { b2s[i]=b2[i]; gos[i]=go[i]; bos[i]=bo[i]; }
    __syncthreads();

    const int wid  = tid >> 5;          // 0..15
    const int lane = tid & 31;
    const int r0   = wid * 8;           // warp's rows within tile
    const int c1   = lane * 4;          // GEMM1 cols
    const int c2   = lane * 8;          // GEMM2 cols
    float* Fw = Fs + wid * (8 * NFEAT);                       // 176 floats
    float2* Hw = (float2*)(hs2 + wid * 1024);                 // [pair*128 + k]
    const unsigned long long* Hw64 = (const unsigned long long*)Hw;

    const int nTiles = (nRows + TM - 1) / TM;

    for (int tile = blockIdx.x; tile < nTiles; tile += gridDim.x) {
        const int rowBase = tile * TM;
        const int wRow = rowBase + r0;

        // per-warp F staging (8 rows x 22, contiguous 176 floats)
        {
            const float* src = &g_F[(size_t)wRow * NFEAT];
            #pragma unroll
            for (int i = lane; i < 8 * NFEAT; i += 32)
                Fw[i] = (wRow + i / NFEAT < nRows) ? src[i] : 0.0f;
        }
        __syncwarp();

        // GEMM1 + bias + GELU -> Hw as row-pair float2 [pair][k]
        {
            float acc[8][4];
            #pragma unroll
            for (int i = 0; i < 8; i++)
                #pragma unroll
                for (int j = 0; j < 4; j++) acc[i][j] = 0.0f;
            #pragma unroll
            for (int k = 0; k < NFEAT; k++) {
                float4 w = *(const float4*)&W1s[k*128 + c1];
                #pragma unroll
                for (int i = 0; i < 8; i++) {
                    float a = Fw[i*NFEAT + k];
                    acc[i][0] = fmaf(a, w.x, acc[i][0]);
                    acc[i][1] = fmaf(a, w.y, acc[i][1]);
                    acc[i][2] = fmaf(a, w.z, acc[i][2]);
                    acc[i][3] = fmaf(a, w.w, acc[i][3]);
                }
            }
            float bv[4] = { b1s[c1], b1s[c1+1], b1s[c1+2], b1s[c1+3] };
            #pragma unroll
            for (int p = 0; p < 4; p++) {
                #pragma unroll
                for (int j = 0; j < 4; j++) {
                    float h0 = geluf(acc[2*p  ][j] + bv[j]);
                    float h1 = geluf(acc[2*p+1][j] + bv[j]);
                    Hw[p*128 + c1 + j] = make_float2(h0, h1);
                }
            }
        }
        __syncwarp();

        // GEMM2: 4 row-pairs x 8 cols; a-operand is a direct 64-bit LDS
        unsigned long long acc2[4][8];
        #pragma unroll
        for (int p = 0; p < 4; p++)
            #pragma unroll
            for (int j = 0; j < 8; j++) acc2[p][j] = 0ull;

        #pragma unroll 4
        for (int k = 0; k < 128; k++) {
            float4 wA = *(const float4*)&W2s[k*256 + c2];
            float4 wB = *(const float4*)&W2s[k*256 + c2 + 4];
            unsigned long long bw[8];
            bw[0] = pk2(wA.x, wA.x); bw[1] = pk2(wA.y, wA.y);
            bw[2] = pk2(wA.z, wA.z); bw[3] = pk2(wA.w, wA.w);
            bw[4] = pk2(wB.x, wB.x); bw[5] = pk2(wB.y, wB.y);
            bw[6] = pk2(wB.z, wB.z); bw[7] = pk2(wB.w, wB.w);
            #pragma unroll
            for (int p = 0; p < 4; p++) {
                unsigned long long a2 = Hw64[p*128 + k];
                #pragma unroll
                for (int j = 0; j < 8; j++)
                    acc2[p][j] = ffma2(a2, bw[j], acc2[p][j]);
            }
        }

        // epilogue: +b2, per-row LayerNorm over 256 (warp = one row group)
        float bb[8], gg[8], oo[8];
        #pragma unroll
        for (int j = 0; j < 8; j++) {
            bb[j] = b2s[c2+j]; gg[j] = gos[c2+j]; oo[j] = bos[c2+j];
        }
        #pragma unroll
        for (int p = 0; p < 4; p++) {
            float vl[8], vh[8];
            #pragma unroll
            for (int j = 0; j < 8; j++) {
                vl[j] = lo2(acc2[p][j]) + bb[j];
                vh[j] = hi2(acc2[p][j]) + bb[j];
            }
            float sl = 0.f, sh = 0.f;
            #pragma unroll
            for (int j = 0; j < 8; j++) { sl += vl[j]; sh += vh[j]; }
            #pragma unroll
            for (int off = 16; off >= 1; off >>= 1) {
                sl += __shfl_xor_sync(0xffffffffu, sl, off);
                sh += __shfl_xor_sync(0xffffffffu, sh, off);
            }
            float mul = sl * (1.0f/256.0f);
            float muh = sh * (1.0f/256.0f);
            float ql = 0.f, qh = 0.f;
            #pragma unroll
            for (int j = 0; j < 8; j++) {
                float dl = vl[j]-mul; ql = fmaf(dl,dl,ql);
                float dh = vh[j]-muh; qh = fmaf(dh,dh,qh);
            }
            #pragma unroll
            for (int off = 16; off >= 1; off >>= 1) {
                ql += __shfl_xor_sync(0xffffffffu, ql, off);
                qh += __shfl_xor_sync(0xffffffffu, qh, off);
            }
            float rsl = rsqrtf(ql * (1.0f/256.0f) + 1e-5f);
            float rsh = rsqrtf(qh * (1.0f/256.0f) + 1e-5f);

            int rowL = wRow + 2*p;
            if (rowL < nRows) {
                float4 o1, o2;
                o1.x = fmaf((vl[0]-mul)*rsl, gg[0], oo[0]);
                o1.y = fmaf((vl[1]-mul)*rsl, gg[1], oo[1]);
                o1.z = fmaf((vl[2]-mul)*rsl, gg[2], oo[2]);
                o1.w = fmaf((vl[3]-mul)*rsl, gg[3], oo[3]);
                o2.x = fmaf((vl[4]-mul)*rsl, gg[4], oo[4]);
                o2.y = fmaf((vl[5]-mul)*rsl, gg[5], oo[5]);
                o2.z = fmaf((vl[6]-mul)*rsl, gg[6], oo[6]);
                o2.w = fmaf((vl[7]-mul)*rsl, gg[7], oo[7]);
                float* op = &out[(size_t)rowL*256 + c2];
                *(float4*)op = o1; *(float4*)(op+4) = o2;
            }
            if (rowL + 1 < nRows) {
                float4 o1, o2;
                o1.x = fmaf((vh[0]-muh)*rsh, gg[0], oo[0]);
                o1.y = fmaf((vh[1]-muh)*rsh, gg[1], oo[1]);
                o1.z = fmaf((vh[2]-muh)*rsh, gg[2], oo[2]);
                o1.w = fmaf((vh[3]-muh)*rsh, gg[3], oo[3]);
                o2.x = fmaf((vh[4]-muh)*rsh, gg[4], oo[4]);
                o2.y = fmaf((vh[5]-muh)*rsh, gg[5], oo[5]);
                o2.z = fmaf((vh[6]-muh)*rsh, gg[6], oo[6]);
                o2.w = fmaf((vh[7]-muh)*rsh, gg[7], oo[7]);
                float* op = &out[(size_t)(rowL+1)*256 + c2];
                *(float4*)op = o1; *(float4*)(op+4) = o2;
            }
        }
        __syncwarp();  // hs2/Fs reuse safety within warp
    }
}

extern "C" void kernel_launch(void* const* d_in, const int* in_sizes, int n_in,
                              void* d_out, int out_size) {
    const float* x  = (const float*)d_in[0];
    const float* gm = (const float*)d_in[1];
    const float* bm = (const float*)d_in[2];
    const float* gs = (const float*)d_in[3];
    const float* bs = (const float*)d_in[4];
    const float* W1 = (const float*)d_in[5];
    const float* b1 = (const float*)d_in[6];
    const float* W2 = (const float*)d_in[7];
    const float* b2 = (const float*)d_in[8];
    const float* go = (const float*)d_in[9];
    const float* bo = (const float*)d_in[10];

    int B = in_sizes[0] / TLEN;
    int nRows = B * NP;

    cudaFuncSetAttribute(mlp_kernel, cudaFuncAttributeMaxDynamicSharedMemorySize,
                         SMEM_FLOATS * (int)sizeof(float));

    feat_kernel<<<B, 256>>>(x, gm, bm, gs, bs);
    mlp_kernel<<<148, 512, SMEM_FLOATS * (int)sizeof(float)>>>(
        W1, b1, W2, b2, go, bo, (float*)d_out, nRows);
}